// round 17
// baseline (speedup 1.0000x reference)
#include <cuda_runtime.h>
#include <cstdint>
#include <math_constants.h>

// Problem constants
#define B_DIM 64
#define S_DIM 2048
#define D_DIM 1024
#define TOTAL_ROWS (B_DIM * S_DIM)          // 131072 flattened rows

// 296 CTAs = 148 SMs x occ 2. CTA c owns flattened rows
// [rlo(c), rlo(c+1)) (~443 rows, spans at most 2 batches -> 1-2 segments).
// NO residency assumption: nothing in this kernel spins on global state.
#define WARPS_PER_CTA 8
#define THREADS (WARPS_PER_CTA * 32)
#define GRID1 296
#define VEC 8                       // 8 float4 = 32 floats per lane
#define NSTAGES 3                   // TMA ring depth per warp
#define CHUNK 8                     // rows per steal grab (smem cursor)
#define ROW_BYTES (D_DIM * 4)       // 4096

#define RING_F4_PER_WARP (NSTAGES * (D_DIM / 4))
#define DYN_SMEM_BYTES (WARPS_PER_CTA * RING_F4_PER_WARP * 16)   // 96 KB

// Scratch (device globals: allocation-free)  ~2.4 MB
__device__ float g_acc[(size_t)GRID1 * 2 * D_DIM];   // slot = 2*cta + seg
__device__ float g_m[GRID1 * 2];
__device__ float g_l[GRID1 * 2];
__device__ int   g_cnt[B_DIM];      // arrivals; last arriver combines + resets

extern __shared__ float4 s_ring[];  // [WARPS_PER_CTA][NSTAGES][D_DIM/4]

__device__ __forceinline__ int rlo(int c) {
    return (int)(((long long)c * TOTAL_ROWS) / GRID1);
}

__device__ __forceinline__ void mbar_wait(uint32_t mbar, uint32_t parity) {
    asm volatile(
        "{\n\t"
        ".reg .pred P;\n\t"
        "W_%=:\n\t"
        "mbarrier.try_wait.parity.acquire.cta.shared::cta.b64 P, [%0], %1, 0x989680;\n\t"
        "@P bra D_%=;\n\t"
        "bra W_%=;\n\t"
        "D_%=:\n\t"
        "}"
        :: "r"(mbar), "r"(parity) : "memory");
}

// ---------------------------------------------------------------------------
// Fused kernel, flat row partitioning, last-arriver combine:
//  - CTA processes its contiguous row range as 1-2 batch-segments.
//  - Within a segment: warps steal CHUNK-row chunks via a SMEM cursor
//    (one-chunk-ahead prefetch), stream rows through a per-warp 3-stage
//    TMA ring (4 KB cp.async.bulk per row).
//  - RING INVARIANT: at segment start pend==0 and all slots are free, so
//    tail is resynced to head (issue order restarts at the wait pointer).
//    Without this, a segment whose prologue issues <NSTAGES rows waits on
//    a slot that was never issued -> deadlock (the R15/R16 hang).
//  - Segment epilogue: in-CTA merge -> one partial per (CTA,seg) slot,
//    then atomicAdd arrival; the LAST arriver combines the batch inline.
// ---------------------------------------------------------------------------
__global__ __launch_bounds__(THREADS, 2)
void luong_fused_kernel(const int*   __restrict__ enc_mask,
                        const float* __restrict__ enc_out,
                        const float* __restrict__ dec_hid,
                        float*       __restrict__ out)
{
    const int tid  = threadIdx.x;
    const int warp = tid >> 5;
    const int lane = tid & 31;

    float4* ring = s_ring + (size_t)warp * RING_F4_PER_WARP;

    __shared__ __align__(8) uint64_t s_mbar[WARPS_PER_CTA][NSTAGES];
    __shared__ float s_m[WARPS_PER_CTA], s_l[WARPS_PER_CTA];
    __shared__ int   s_cur;
    __shared__ int   s_last;

    if (lane == 0) {
        #pragma unroll
        for (int st = 0; st < NSTAGES; st++) {
            uint32_t mb = (uint32_t)__cvta_generic_to_shared(&s_mbar[warp][st]);
            asm volatile("mbarrier.init.shared.b64 [%0], 1;" :: "r"(mb) : "memory");
        }
    }
    __syncwarp();

    const int r_begin = rlo(blockIdx.x);
    const int r_end   = rlo(blockIdx.x + 1);
    const int b_first = r_begin / S_DIM;
    const int b_last  = (r_end - 1) / S_DIM;
    const int nseg    = (b_first == b_last) ? 1 : 2;

    // Ring bookkeeping (per-slot phase parity persists across segments).
    int head = 0, tail = 0;
    unsigned ph = 0;

    for (int seg = 0; seg < nseg; seg++) {
        const int batch   = b_first + seg;
        const int s_begin = (seg == 0) ? r_begin : (b_first + 1) * S_DIM;
        const int s_end   = (seg == 0 && nseg == 2) ? (b_first + 1) * S_DIM : r_end;
        const int nrows   = s_end - s_begin;

        tail = head;                        // resync: issue order restarts
                                            // at the wait pointer (BUGFIX)

        if (tid == 0) s_cur = 0;
        __syncthreads();                    // cursor ready; prior ring use done

        // dec_hid slice for this segment's batch
        float4 h[VEC];
        {
            const float4* hp = reinterpret_cast<const float4*>(
                dec_hid + (size_t)batch * D_DIM);
            #pragma unroll
            for (int i = 0; i < VEC; i++) h[i] = hp[i * 32 + lane];
        }

        // --- smem-cursor stealing with one-chunk-ahead prefetch ---
        auto fetch = [&](uint32_t& bits, int& cb) -> bool {
            int c = 0;
            if (lane == 0) c = atomicAdd(&s_cur, CHUNK);
            c = __shfl_sync(0xFFFFFFFFu, c, 0);
            if (c >= nrows) { bits = 0u; return false; }
            cb = s_begin + c;
            const bool un = (lane < CHUNK) && (cb + lane < s_end) &&
                            (__ldg(enc_mask + cb + lane) == 0);
            bits = __ballot_sync(0xFFFFFFFFu, un);
            return true;
        };

        uint32_t cur_bits = 0u, nxt_bits = 0u;
        int      cur_base = 0,  nxt_base = 0;
        bool     have_nxt;

        have_nxt = fetch(cur_bits, cur_base);
        if (have_nxt) have_nxt = fetch(nxt_bits, nxt_base);

        auto next_row = [&]() -> int {      // next unmasked absolute row or -1
            while (cur_bits == 0u) {
                if (!have_nxt) return -1;
                cur_bits = nxt_bits;
                cur_base = nxt_base;
                have_nxt = fetch(nxt_bits, nxt_base);
            }
            const int r = cur_base + __ffs(cur_bits) - 1;
            cur_bits &= cur_bits - 1u;
            return r;
        };

        auto issue = [&](int st, int r) {   // 4 KB TMA bulk, lane 0 only
            if (lane == 0) {
                uint32_t mb  = (uint32_t)__cvta_generic_to_shared(&s_mbar[warp][st]);
                uint32_t dst = (uint32_t)__cvta_generic_to_shared(
                    ring + st * (D_DIM / 4));
                const float* src = enc_out + (size_t)r * D_DIM;
                asm volatile("mbarrier.arrive.expect_tx.shared.b64 _, [%0], %1;"
                             :: "r"(mb), "r"((uint32_t)ROW_BYTES) : "memory");
                asm volatile("cp.async.bulk.shared::cta.global.mbarrier::complete_tx::bytes "
                             "[%0], [%1], %2, [%3];"
                             :: "r"(dst), "l"(src), "r"((uint32_t)ROW_BYTES), "r"(mb)
                             : "memory");
            }
        };

        float m = -CUDART_INF_F;
        float l = 0.0f;
        float acc[VEC * 4];
        #pragma unroll
        for (int j = 0; j < VEC * 4; j++) acc[j] = 0.0f;

        // Prologue: fill ring
        int r = next_row();
        int pend = 0;
        while (r >= 0 && pend < NSTAGES) {
            issue(tail, r);
            tail = (tail + 1 == NSTAGES) ? 0 : tail + 1;
            pend++;
            r = next_row();
        }

        // Mainloop
        while (pend > 0) {
            {
                uint32_t mb = (uint32_t)__cvta_generic_to_shared(&s_mbar[warp][head]);
                mbar_wait(mb, (ph >> head) & 1u);
                ph ^= 1u << head;
            }
            pend--;

            const float4* xs = ring + head * (D_DIM / 4);

            float d0 = 0.f, d1 = 0.f, d2 = 0.f, d3 = 0.f;
            #pragma unroll
            for (int i = 0; i < VEC; i++) {
                const float4 v = xs[i * 32 + lane];
                d0 = fmaf(v.x, h[i].x, d0);
                d1 = fmaf(v.y, h[i].y, d1);
                d2 = fmaf(v.z, h[i].z, d2);
                d3 = fmaf(v.w, h[i].w, d3);
            }
            float dsum = (d0 + d1) + (d2 + d3);
            #pragma unroll
            for (int o = 16; o > 0; o >>= 1)
                dsum += __shfl_xor_sync(0xFFFFFFFFu, dsum, o);

            if (dsum > m) {                 // warp-uniform; ~log(n) times
                const float scale = __expf(m - dsum);
                l *= scale;
                #pragma unroll
                for (int j = 0; j < VEC * 4; j++) acc[j] *= scale;
                m = dsum;
            }
            const float p = __expf(dsum - m);
            l += p;
            #pragma unroll
            for (int i = 0; i < VEC; i++) {
                const float4 v = xs[i * 32 + lane];
                acc[i * 4 + 0] = fmaf(p, v.x, acc[i * 4 + 0]);
                acc[i * 4 + 1] = fmaf(p, v.y, acc[i * 4 + 1]);
                acc[i * 4 + 2] = fmaf(p, v.z, acc[i * 4 + 2]);
                acc[i * 4 + 3] = fmaf(p, v.w, acc[i * 4 + 3]);
            }

            if (r >= 0) {
                issue(head, r);             // refill the just-freed slot
                tail = (head + 1 == NSTAGES) ? 0 : head + 1;  // keep tail glued
                pend++;
                r = next_row();
            }
            head = (head + 1 == NSTAGES) ? 0 : head + 1;
        }

        // ---- In-CTA merge for this segment -> slot 2*cta+seg ----
        if (lane == 0) { s_m[warp] = m; s_l[warp] = l; }
        __syncthreads();

        float m_cta = -CUDART_INF_F;
        #pragma unroll
        for (int i = 0; i < WARPS_PER_CTA; i++) m_cta = fmaxf(m_cta, s_m[i]);
        float l_cta = 0.0f;
        #pragma unroll
        for (int i = 0; i < WARPS_PER_CTA; i++) {
            const float wi = (s_l[i] > 0.0f) ? __expf(s_m[i] - m_cta) : 0.0f;
            l_cta = fmaf(s_l[i], wi, l_cta);
        }
        const float w_me = (l > 0.0f) ? __expf(m - m_cta) : 0.0f;

        #pragma unroll
        for (int i = 0; i < VEC; i++) {
            float4 v;
            v.x = acc[i * 4 + 0] * w_me; v.y = acc[i * 4 + 1] * w_me;
            v.z = acc[i * 4 + 2] * w_me; v.w = acc[i * 4 + 3] * w_me;
            ring[i * 32 + lane] = v;
        }
        __syncthreads();

        const int slot = blockIdx.x * 2 + seg;
        {
            const int fi = warp * 32 + lane;
            float4 sum = s_ring[fi];
            #pragma unroll
            for (int w = 1; w < WARPS_PER_CTA; w++) {
                const float4 a = s_ring[(size_t)w * RING_F4_PER_WARP + fi];
                sum.x += a.x; sum.y += a.y; sum.z += a.z; sum.w += a.w;
            }
            reinterpret_cast<float4*>(g_acc + (size_t)slot * D_DIM)[fi] = sum;
        }
        if (tid == 0) {
            g_m[slot] = m_cta;
            g_l[slot] = l_cta;
        }
        __threadfence();                    // release partial
        __syncthreads();

        // ---- Contributor range of this batch (closed-form, all threads) ----
        const int row_lo = batch * S_DIM;
        const int row_hi = row_lo + S_DIM;
        int c_first = (int)(((long long)row_lo * GRID1) / TOTAL_ROWS);
        while (rlo(c_first + 1) <= row_lo) c_first++;
        int c_last = (int)(((long long)(row_hi - 1) * GRID1) / TOTAL_ROWS);
        while (rlo(c_last + 1) <= row_hi - 1) c_last++;
        const int nparts = c_last - c_first + 1;      // <= 6

        if (tid == 0) {
            const int old = atomicAdd(&g_cnt[batch], 1);
            s_last = (old == nparts - 1);
        }
        __syncthreads();

        // ---- Last arriver combines this batch inline (no spinning) ----
        if (s_last) {
            __threadfence();                // acquire all partials

            float mg = -CUDART_INF_F;
            for (int c = c_first; c <= c_last; c++) {
                const int sg = (rlo(c) / S_DIM == batch) ? 0 : 1;
                mg = fmaxf(mg, g_m[c * 2 + sg]);
            }
            float ltot = 0.0f;
            for (int c = c_first; c <= c_last; c++) {
                const int sg = (rlo(c) / S_DIM == batch) ? 0 : 1;
                const float lj = g_l[c * 2 + sg];
                const float wj = (lj > 0.0f) ? __expf(g_m[c * 2 + sg] - mg) : 0.0f;
                ltot = fmaf(lj, wj, ltot);
            }
            const float inv = 1.0f / ltot;

            float4 rr = make_float4(0.f, 0.f, 0.f, 0.f);
            for (int c = c_first; c <= c_last; c++) {
                const int sg = (rlo(c) / S_DIM == batch) ? 0 : 1;
                const int sl = c * 2 + sg;
                const float lj = g_l[sl];
                const float wj = (lj > 0.0f) ? __expf(g_m[sl] - mg) : 0.0f;
                const float4 a = reinterpret_cast<const float4*>(
                    g_acc + (size_t)sl * D_DIM)[tid];
                rr.x = fmaf(a.x, wj, rr.x);
                rr.y = fmaf(a.y, wj, rr.y);
                rr.z = fmaf(a.z, wj, rr.z);
                rr.w = fmaf(a.w, wj, rr.w);
            }
            rr.x *= inv; rr.y *= inv; rr.z *= inv; rr.w *= inv;
            reinterpret_cast<float4*>(out + (size_t)batch * D_DIM)[tid] = rr;

            if (tid == 0) g_cnt[batch] = 0;     // reset for next graph replay
        }
    }
}

// ---------------------------------------------------------------------------
// Launch.  Inputs bound by element count:
//   B*S   = 131072    -> enc_mask (int32; JAX bool materialized as int32)
//   B*S*D = 134217728 -> enc_out  (f32)
//   B*D   = 65536     -> dec_hid  (f32)
// ---------------------------------------------------------------------------
extern "C" void kernel_launch(void* const* d_in, const int* in_sizes, int n_in,
                              void* d_out, int out_size)
{
    const int*   enc_mask = nullptr;
    const float* enc_out  = nullptr;
    const float* dec_hid  = nullptr;

    for (int i = 0; i < n_in; i++) {
        if (in_sizes[i] == B_DIM * S_DIM)            enc_mask = (const int*)d_in[i];
        else if (in_sizes[i] == B_DIM * D_DIM)       dec_hid  = (const float*)d_in[i];
        else                                          enc_out  = (const float*)d_in[i];
    }

    cudaFuncSetAttribute(luong_fused_kernel,
                         cudaFuncAttributeMaxDynamicSharedMemorySize,
                         DYN_SMEM_BYTES);

    luong_fused_kernel<<<GRID1, THREADS, DYN_SMEM_BYTES>>>(
        enc_mask, enc_out, dec_hid, (float*)d_out);
}